// round 5
// baseline (speedup 1.0000x reference)
#include <cuda_runtime.h>
#include <cuda_bf16.h>

#define BB 4
#define SS 1024
#define HH 16
#define HDIM 64
#define DD 1024

// ---------------------------------------------------------------------------
// scratch (device globals — no allocation allowed)
// ---------------------------------------------------------------------------
__device__ float g_qkv[BB * SS * 3 * DD];   // [B,S,3D] fp32 (for vT)
__device__ __nv_bfloat16 g_xhi[BB * SS * DD];
__device__ __nv_bfloat16 g_xlo[BB * SS * DD];
__device__ __nv_bfloat16 g_wqT_hi[3 * DD * DD];
__device__ __nv_bfloat16 g_wqT_lo[3 * DD * DD];
__device__ __nv_bfloat16 g_woT_hi[DD * DD];
__device__ __nv_bfloat16 g_woT_lo[DD * DD];
__device__ __nv_bfloat16 g_vhi[BB * SS * DD];   // values hi (attn epilogue)
__device__ __nv_bfloat16 g_vlo[BB * SS * DD];
__device__ __nv_bfloat16 g_qh[BB * SS * 3 * DD];   // qkv split hi (gemm epilogue)
__device__ __nv_bfloat16 g_ql[BB * SS * 3 * DD];
__device__ __nv_bfloat16 g_vTh[BB * HH * HDIM * SS]; // V^T per (b,h): [64][S]
__device__ __nv_bfloat16 g_vTl[BB * HH * HDIM * SS];

// ---------------------------------------------------------------------------
__device__ __forceinline__ unsigned smem_u32(const void* p) {
    unsigned a;
    asm("{ .reg .u64 t; cvta.to.shared.u64 t, %1; cvt.u32.u64 %0, t; }" : "=r"(a) : "l"(p));
    return a;
}
#define SWZ128(o) ((o) ^ (((o) >> 3) & 0x70))

#define CP_ASYNC16(saddr, gptr) \
    asm volatile("cp.async.cg.shared.global [%0], [%1], 16;" :: "r"(saddr), "l"(gptr) : "memory")
#define CP_COMMIT() asm volatile("cp.async.commit_group;" ::: "memory")
#define CP_WAIT1()  asm volatile("cp.async.wait_group 1;" ::: "memory")
#define CP_WAIT0()  asm volatile("cp.async.wait_group 0;" ::: "memory")

#define LDMX4(r0, r1, r2, r3, a) \
    asm volatile("ldmatrix.sync.aligned.m8n8.x4.shared.b16 {%0,%1,%2,%3}, [%4];" \
        : "=r"(r0), "=r"(r1), "=r"(r2), "=r"(r3) : "r"(a))

#define MMA16816(d, a, b0, b1) \
    asm volatile("mma.sync.aligned.m16n8k16.row.col.f32.bf16.bf16.f32 " \
        "{%0,%1,%2,%3}, {%4,%5,%6,%7}, {%8,%9}, {%0,%1,%2,%3};" \
        : "+f"((d)[0]), "+f"((d)[1]), "+f"((d)[2]), "+f"((d)[3]) \
        : "r"((a)[0]), "r"((a)[1]), "r"((a)[2]), "r"((a)[3]), "r"(b0), "r"(b1))

__device__ __forceinline__ unsigned pack_hi2(float x, float y, unsigned& lo) {
    __nv_bfloat16 hx = __float2bfloat16(x);
    __nv_bfloat16 hy = __float2bfloat16(y);
    __nv_bfloat16 lx = __float2bfloat16(x - __bfloat162float(hx));
    __nv_bfloat16 ly = __float2bfloat16(y - __bfloat162float(hy));
    lo = ((unsigned)__bfloat16_as_ushort(ly) << 16) | __bfloat16_as_ushort(lx);
    return ((unsigned)__bfloat16_as_ushort(hy) << 16) | __bfloat16_as_ushort(hx);
}

// ---------------------------------------------------------------------------
__global__ __launch_bounds__(256) void split_kernel(
    const float* __restrict__ src, __nv_bfloat16* __restrict__ hi,
    __nv_bfloat16* __restrict__ lo, int n4)
{
    int i = blockIdx.x * 256 + threadIdx.x;
    if (i >= n4) return;
    float4 v = ((const float4*)src)[i];
    unsigned l0, l1, h0, h1;
    h0 = pack_hi2(v.x, v.y, l0);
    h1 = pack_hi2(v.z, v.w, l1);
    ((uint2*)hi)[i] = make_uint2(h0, h1);
    ((uint2*)lo)[i] = make_uint2(l0, l1);
}

__global__ __launch_bounds__(256) void tsplit_kernel(
    const float* __restrict__ W, __nv_bfloat16* __restrict__ hiT,
    __nv_bfloat16* __restrict__ loT, int K, int N)
{
    __shared__ float t[32][33];
    int k0 = blockIdx.y * 32, n0 = blockIdx.x * 32;
    int tx = threadIdx.x, ty = threadIdx.y;
    #pragma unroll
    for (int i = 0; i < 32; i += 8)
        t[ty + i][tx] = W[(size_t)(k0 + ty + i) * N + n0 + tx];
    __syncthreads();
    #pragma unroll
    for (int i = 0; i < 32; i += 8) {
        float v = t[tx][ty + i];
        __nv_bfloat16 h = __float2bfloat16(v);
        size_t o = (size_t)(n0 + ty + i) * K + k0 + tx;
        hiT[o] = h;
        loT[o] = __float2bfloat16(v - __bfloat162float(h));
    }
}

// V^T + split: qkv V slice -> vT hi/lo [bh][64][S]
__global__ __launch_bounds__(256) void vT_kernel(
    const float* __restrict__ qkv, __nv_bfloat16* __restrict__ vTh,
    __nv_bfloat16* __restrict__ vTl)
{
    __shared__ float t[32][33];
    int s0 = blockIdx.x * 32, d0 = blockIdx.y * 32, bh = blockIdx.z;
    int b = bh >> 4, h = bh & 15;
    int tx = threadIdx.x, ty = threadIdx.y;
    #pragma unroll
    for (int i = 0; i < 32; i += 8)
        t[ty + i][tx] = qkv[(size_t)(b * SS + s0 + ty + i) * 3072 + h * 192 + 128 + d0 + tx];
    __syncthreads();
    #pragma unroll
    for (int i = 0; i < 32; i += 8) {
        float v = t[tx][ty + i];
        __nv_bfloat16 hh = __float2bfloat16(v);
        size_t o = (size_t)(bh * HDIM + d0 + ty + i) * SS + s0 + tx;
        vTh[o] = hh;
        vTl[o] = __float2bfloat16(v - __bfloat162float(hh));
    }
}

// ---------------------------------------------------------------------------
// mma.sync GEMM, 3xBF16 split, 3-stage cp.async pipeline.
// C = Ahi@BThi^T + Alo@BThi^T + Ahi@BTlo^T + bias (optionally also hi/lo split out)
// ---------------------------------------------------------------------------
#define GT_STAGE 32768
#define GT_TOTAL 98304

__device__ __forceinline__ void prefetch_tile(
    const __nv_bfloat16* __restrict__ A, const __nv_bfloat16* __restrict__ BT,
    int brow, int bcol, int K, int kt, unsigned stage, int tid)
{
    #pragma unroll
    for (int i = 0; i < 4; i++) {
        int idx = tid + i * 256;
        int row = idx >> 3;
        int c16 = (idx & 7) * 16;
        unsigned soff = SWZ128((unsigned)(row * 128 + c16));
        CP_ASYNC16(stage + soff, (const char*)(A + (size_t)(brow + row) * K + kt) + c16);
    }
    #pragma unroll
    for (int i = 0; i < 4; i++) {
        int idx = tid + i * 256;
        int row = idx >> 3;
        int c16 = (idx & 7) * 16;
        unsigned soff = SWZ128((unsigned)(row * 128 + c16));
        CP_ASYNC16(stage + 16384 + soff, (const char*)(BT + (size_t)(bcol + row) * K + kt) + c16);
    }
}

__global__ __launch_bounds__(256) void gemm3x_mma(
    const __nv_bfloat16* __restrict__ Ahi, const __nv_bfloat16* __restrict__ Alo,
    const __nv_bfloat16* __restrict__ BThi, const __nv_bfloat16* __restrict__ BTlo,
    const float* __restrict__ bias, float* __restrict__ C,
    __nv_bfloat16* __restrict__ Chi, __nv_bfloat16* __restrict__ Clo,
    int M, int N, int K)
{
    extern __shared__ char smem[];
    unsigned sb = smem_u32(smem);
    const int tid = threadIdx.x, w = tid >> 5, lane = tid & 31;
    const int brow = blockIdx.y * 128, bcol = blockIdx.x * 128;

    const __nv_bfloat16* Ap[3] = {Ahi, Alo, Ahi};
    const __nv_bfloat16* Bp[3] = {BThi, BThi, BTlo};

    const int nk = K >> 6;
    const int nch = 3 * nk;
    const int wm = (w >> 2) * 64;
    const int wn = (w & 3) * 32;
    const int lrow = lane & 15;
    const int lcolB = (lane >> 4) * 16;

    float acc[4][4][4] = {};

    prefetch_tile(Ap[0], Bp[0], brow, bcol, K, 0, sb, tid);
    CP_COMMIT();
    prefetch_tile(Ap[1 / nk], Bp[1 / nk], brow, bcol, K, (1 % nk) << 6, sb + GT_STAGE, tid);
    CP_COMMIT();
    CP_WAIT1();
    __syncthreads();

    int stage = 0;
    for (int c = 0; c < nch; c++) {
        // issue prefetch for c+2 before MMA so loads overlap tensor work
        if (c + 2 < nch) {
            int cn = c + 2;
            int p = cn / nk, kt = (cn - p * nk) << 6;
            int st2 = stage + 2; if (st2 >= 3) st2 -= 3;
            prefetch_tile(Ap[p], Bp[p], brow, bcol, K, kt, sb + st2 * GT_STAGE, tid);
            CP_COMMIT();
        }

        unsigned baseA = sb + stage * GT_STAGE;
        unsigned baseB = baseA + 16384;
        #pragma unroll
        for (int ks = 0; ks < 4; ks++) {
            int kb = ks * 32;
            unsigned afr[4][4];
            unsigned bfr[2][4];
            #pragma unroll
            for (int i = 0; i < 4; i++) {
                unsigned off = (unsigned)((wm + i * 16 + lrow) * 128 + kb + lcolB);
                LDMX4(afr[i][0], afr[i][1], afr[i][2], afr[i][3], baseA + SWZ128(off));
            }
            #pragma unroll
            for (int j2 = 0; j2 < 2; j2++) {
                unsigned off = (unsigned)((wn + j2 * 16 + lrow) * 128 + kb + lcolB);
                LDMX4(bfr[j2][0], bfr[j2][1], bfr[j2][2], bfr[j2][3], baseB + SWZ128(off));
            }
            #pragma unroll
            for (int i = 0; i < 4; i++) {
                #pragma unroll
                for (int j = 0; j < 4; j++) {
                    unsigned b0 = (j & 1) ? bfr[j >> 1][1] : bfr[j >> 1][0];
                    unsigned b1 = (j & 1) ? bfr[j >> 1][3] : bfr[j >> 1][2];
                    MMA16816(acc[i][j], afr[i], b0, b1);
                }
            }
        }

        if (c + 1 < nch) {
            if (c + 2 < nch) { CP_WAIT1(); } else { CP_WAIT0(); }
        }
        __syncthreads();
        if (++stage == 3) stage = 0;
    }

    const int r0 = brow + wm + (lane >> 2);
    const int c0 = bcol + wn + (lane & 3) * 2;
    #pragma unroll
    for (int i = 0; i < 4; i++) {
        #pragma unroll
        for (int j = 0; j < 4; j++) {
            int col = c0 + j * 8;
            float bx = bias[col], by = bias[col + 1];
            float v00 = acc[i][j][0] + bx, v01 = acc[i][j][1] + by;
            float v10 = acc[i][j][2] + bx, v11 = acc[i][j][3] + by;
            size_t o0 = (size_t)(r0 + i * 16) * N + col;
            size_t o1 = (size_t)(r0 + i * 16 + 8) * N + col;
            *(float2*)&C[o0] = make_float2(v00, v01);
            *(float2*)&C[o1] = make_float2(v10, v11);
            if (Chi) {
                unsigned l0, l1;
                unsigned h0 = pack_hi2(v00, v01, l0);
                unsigned h1 = pack_hi2(v10, v11, l1);
                *(unsigned*)&Chi[o0] = h0;
                *(unsigned*)&Clo[o0] = l0;
                *(unsigned*)&Chi[o1] = h1;
                *(unsigned*)&Clo[o1] = l1;
            }
        }
    }
}

// ---------------------------------------------------------------------------
// Tensorized fused attention (single barrier per chunk; double-buffered P cvt)
// ---------------------------------------------------------------------------
#define AT_QH   131072
#define AT_QL   135168
#define AT_K0   139264     // 2 x 32768 region (K: hi16K+lo16K / V: hi8K+lo8K)
#define AT_PH   204800     // PH(bb)=AT_PH+bb*8192, PL(bb)=AT_PH+4096+bb*8192
#define AT_TOTAL 221184

__device__ __forceinline__ void attn_load_k(
    const __nv_bfloat16* __restrict__ qh, const __nv_bfloat16* __restrict__ ql,
    int b, int h, int kb, unsigned dstH, unsigned dstL, int tid)
{
    #pragma unroll
    for (int i = 0; i < 4; i++) {
        int idx = tid + i * 256;
        int row = idx >> 3, c16 = (idx & 7) * 16;
        unsigned so = SWZ128((unsigned)(row * 128 + c16));
        CP_ASYNC16(dstH + so, (const char*)(qh + (size_t)(b * SS + kb + row) * 3072 + h * 192 + 64) + c16);
        CP_ASYNC16(dstL + so, (const char*)(ql + (size_t)(b * SS + kb + row) * 3072 + h * 192 + 64) + c16);
    }
}

__device__ __forceinline__ void attn_load_v(
    const __nv_bfloat16* __restrict__ vTh, const __nv_bfloat16* __restrict__ vTl,
    int bh, int kb, unsigned dstH, unsigned dstL, int tid)
{
    #pragma unroll
    for (int i = 0; i < 2; i++) {
        int idx = tid + i * 256;
        int row = idx >> 3, c16 = (idx & 7) * 16;
        unsigned so = SWZ128((unsigned)(row * 128 + c16));
        CP_ASYNC16(dstH + so, (const char*)(vTh + (size_t)(bh * HDIM + row) * SS + kb) + c16);
        CP_ASYNC16(dstL + so, (const char*)(vTl + (size_t)(bh * HDIM + row) * SS + kb) + c16);
    }
}

__device__ __forceinline__ void convertP(const float* sP, char* smem, int chunk,
                                         int bb, int tid)
{
    unsigned baseH = (unsigned)(AT_PH + bb * 8192);
    unsigned baseL = baseH + 4096;
    #pragma unroll
    for (int i = 0; i < 4; i++) {
        int fid = tid + i * 256;
        int row = fid >> 5;
        int pr = (fid & 31) * 2;
        float2 v = *(const float2*)&sP[row * SS + chunk * 64 + pr];
        unsigned lp;
        unsigned hp = pack_hi2(v.x, v.y, lp);
        unsigned so = SWZ128((unsigned)(row * 128 + pr * 2));
        *(unsigned*)(smem + baseH + so) = hp;
        *(unsigned*)(smem + baseL + so) = lp;
    }
}

__global__ __launch_bounds__(256) void attn_mma(
    const __nv_bfloat16* __restrict__ qh, const __nv_bfloat16* __restrict__ ql,
    const __nv_bfloat16* __restrict__ vTh, const __nv_bfloat16* __restrict__ vTl,
    float* __restrict__ attn_out)
{
    extern __shared__ char smem[];
    unsigned sb = smem_u32(smem);
    float* sP = (float*)smem;

    const int qt = blockIdx.x, h = blockIdx.y, b = blockIdx.z;
    const int bh = b * HH + h;
    const int q0 = qt * 32;
    const int tid = threadIdx.x, w = tid >> 5, lane = tid & 31;
    const int lrow = lane & 15, lcol = (lane >> 4) * 16;

    // ---- prologue: Q tile + K chunks 0,1
    {
        int row = tid >> 3, c16 = (tid & 7) * 16;
        unsigned so = SWZ128((unsigned)(row * 128 + c16));
        CP_ASYNC16(sb + AT_QH + so, (const char*)(qh + (size_t)(b * SS + q0 + row) * 3072 + h * 192) + c16);
        CP_ASYNC16(sb + AT_QL + so, (const char*)(ql + (size_t)(b * SS + q0 + row) * 3072 + h * 192) + c16);
    }
    attn_load_k(qh, ql, b, h, 0, sb + AT_K0, sb + AT_K0 + 16384, tid);
    CP_COMMIT();
    attn_load_k(qh, ql, b, h, 128, sb + AT_K0 + 32768, sb + AT_K0 + 49152, tid);
    CP_COMMIT();
    CP_WAIT1();
    __syncthreads();

    // ---- phase 1: logits = 0.125 * Q K^T  (8 chunks of 128 keys)
    const int wm = (w >> 2) * 16;
    const int wn = (w & 3) * 32;
    for (int c = 0; c < 8; c++) {
        unsigned bufH = sb + AT_K0 + (c & 1) * 32768;
        unsigned bufL = bufH + 16384;
        float acc[4][4] = {};
        #pragma unroll
        for (int p = 0; p < 3; p++) {
            unsigned aBase = sb + (p == 1 ? AT_QL : AT_QH);
            unsigned bBase = (p == 2) ? bufL : bufH;
            #pragma unroll
            for (int ks = 0; ks < 4; ks++) {
                int kb = ks * 32;
                unsigned afr[4];
                LDMX4(afr[0], afr[1], afr[2], afr[3],
                      aBase + SWZ128((unsigned)((wm + lrow) * 128 + kb + lcol)));
                unsigned bfr[2][4];
                #pragma unroll
                for (int j2 = 0; j2 < 2; j2++)
                    LDMX4(bfr[j2][0], bfr[j2][1], bfr[j2][2], bfr[j2][3],
                          bBase + SWZ128((unsigned)((wn + j2 * 16 + lrow) * 128 + kb + lcol)));
                #pragma unroll
                for (int j = 0; j < 4; j++) {
                    unsigned b0 = (j & 1) ? bfr[j >> 1][1] : bfr[j >> 1][0];
                    unsigned b1 = (j & 1) ? bfr[j >> 1][3] : bfr[j >> 1][2];
                    MMA16816(acc[j], afr, b0, b1);
                }
            }
        }
        int r0 = wm + (lane >> 2);
        int cb = c * 128 + wn + (lane & 3) * 2;
        #pragma unroll
        for (int j = 0; j < 4; j++) {
            int col = cb + j * 8;
            *(float2*)&sP[r0 * SS + col]       = make_float2(acc[j][0] * 0.125f, acc[j][1] * 0.125f);
            *(float2*)&sP[(r0 + 8) * SS + col] = make_float2(acc[j][2] * 0.125f, acc[j][3] * 0.125f);
        }
        if (c + 1 < 8) { CP_WAIT0(); }
        __syncthreads();
        if (c + 2 < 8) {
            unsigned nb = sb + AT_K0 + (c & 1) * 32768;
            attn_load_k(qh, ql, b, h, (c + 2) * 128, nb, nb + 16384, tid);
            CP_COMMIT();
        }
    }

    // ---- prefetch V chunks 0,1 (overlaps softmax)
    attn_load_v(vTh, vTl, bh, 0, sb + AT_K0, sb + AT_K0 + 8192, tid);
    CP_COMMIT();
    attn_load_v(vTh, vTl, bh, 64, sb + AT_K0 + 32768, sb + AT_K0 + 40960, tid);
    CP_COMMIT();

    // ---- phase 2: softmax; write normalized P to gmem and back to sP
    for (int r = w; r < 32; r += 8) {
        float* row = &sP[r * SS];
        float m = -1e30f;
        for (int cc = lane; cc < SS; cc += 32) m = fmaxf(m, row[cc]);
        #pragma unroll
        for (int o = 16; o > 0; o >>= 1) m = fmaxf(m, __shfl_xor_sync(0xFFFFFFFFu, m, o));
        float sum = 0.f;
        for (int cc = lane; cc < SS; cc += 32) {
            float e = __expf(row[cc] - m);
            row[cc] = e;
            sum += e;
        }
        #pragma unroll
        for (int o = 16; o > 0; o >>= 1) sum += __shfl_xor_sync(0xFFFFFFFFu, sum, o);
        float inv = 1.0f / sum;
        size_t base = ((size_t)(bh * SS) + q0 + r) * SS;
        for (int cc = lane; cc < SS; cc += 32) {
            float val = row[cc] * inv;
            row[cc] = val;
            attn_out[base + cc] = val;
        }
    }
    __syncthreads();               // all softmax rows final

    // pre-convert chunk 0; ensure V chunk 0 arrived
    convertP(sP, smem, 0, 0, tid);
    CP_WAIT1();
    __syncthreads();

    // ---- phase 3: AV (16 chunks of 64 keys)
    const int wmv = (w >> 2) * 16;
    const int wnv = (w & 3) * 16;
    float vac[2][4] = {};
    for (int c = 0; c < 16; c++) {
        int bb = c & 1;
        unsigned vbH = sb + AT_K0 + bb * 32768;
        unsigned vbL = vbH + 8192;
        unsigned pH = sb + AT_PH + bb * 8192;
        unsigned pL = pH + 4096;
        #pragma unroll
        for (int p = 0; p < 3; p++) {
            unsigned aBase = (p == 1) ? pL : pH;
            unsigned bBase = (p == 2) ? vbL : vbH;
            #pragma unroll
            for (int ks = 0; ks < 4; ks++) {
                int kb = ks * 32;
                unsigned afr[4];
                LDMX4(afr[0], afr[1], afr[2], afr[3],
                      aBase + SWZ128((unsigned)((wmv + lrow) * 128 + kb + lcol)));
                unsigned bfr[4];
                LDMX4(bfr[0], bfr[1], bfr[2], bfr[3],
                      bBase + SWZ128((unsigned)((wnv + lrow) * 128 + kb + lcol)));
                MMA16816(vac[0], afr, bfr[0], bfr[2]);
                MMA16816(vac[1], afr, bfr[1], bfr[3]);
            }
        }
        if (c + 1 < 16) {
            convertP(sP, smem, c + 1, bb ^ 1, tid);   // overlaps; distinct buffers
            CP_WAIT0();                                // V chunk c+1 arrived
        }
        __syncthreads();
        if (c + 2 < 16) {
            unsigned nb = sb + AT_K0 + bb * 32768;
            attn_load_v(vTh, vTl, bh, (c + 2) * 64, nb, nb + 8192, tid);
            CP_COMMIT();
        }
    }

    // ---- epilogue: write values directly as bf16 hi/lo (head-interleaved)
    {
        int r0 = wmv + (lane >> 2);
        int c0 = wnv + (lane & 3) * 2;
        #pragma unroll
        for (int j = 0; j < 2; j++) {
            int col = h * 64 + c0 + j * 8;
            size_t o0 = (size_t)(b * SS + q0 + r0) * DD + col;
            size_t o1 = (size_t)(b * SS + q0 + r0 + 8) * DD + col;
            unsigned l0, l1;
            unsigned h0 = pack_hi2(vac[j][0], vac[j][1], l0);
            unsigned h1 = pack_hi2(vac[j][2], vac[j][3], l1);
            *(unsigned*)&g_vhi[o0] = h0;
            *(unsigned*)&g_vlo[o0] = l0;
            *(unsigned*)&g_vhi[o1] = h1;
            *(unsigned*)&g_vlo[o1] = l1;
        }
    }
}

// ---------------------------------------------------------------------------
extern "C" void kernel_launch(void* const* d_in, const int* in_sizes, int n_in,
                              void* d_out, int out_size)
{
    const float* x     = (const float*)d_in[0];
    const float* W_qkv = (const float*)d_in[1];
    const float* b_qkv = (const float*)d_in[2];
    const float* W_o   = (const float*)d_in[3];
    const float* b_o   = (const float*)d_in[4];

    float* out_o    = (float*)d_out;
    float* out_attn = (float*)d_out + (size_t)BB * SS * DD;

    float* qkv_ptr;
    __nv_bfloat16 *xhi, *xlo, *wqh, *wql, *woh, *wol, *vhi, *vlo;
    __nv_bfloat16 *qhp, *qlp, *vthp, *vtlp;
    cudaGetSymbolAddress((void**)&qkv_ptr, g_qkv);
    cudaGetSymbolAddress((void**)&xhi, g_xhi);
    cudaGetSymbolAddress((void**)&xlo, g_xlo);
    cudaGetSymbolAddress((void**)&wqh, g_wqT_hi);
    cudaGetSymbolAddress((void**)&wql, g_wqT_lo);
    cudaGetSymbolAddress((void**)&woh, g_woT_hi);
    cudaGetSymbolAddress((void**)&wol, g_woT_lo);
    cudaGetSymbolAddress((void**)&vhi, g_vhi);
    cudaGetSymbolAddress((void**)&vlo, g_vlo);
    cudaGetSymbolAddress((void**)&qhp, g_qh);
    cudaGetSymbolAddress((void**)&qlp, g_ql);
    cudaGetSymbolAddress((void**)&vthp, g_vTh);
    cudaGetSymbolAddress((void**)&vtlp, g_vTl);

    cudaFuncSetAttribute(gemm3x_mma, cudaFuncAttributeMaxDynamicSharedMemorySize, GT_TOTAL);
    cudaFuncSetAttribute(attn_mma, cudaFuncAttributeMaxDynamicSharedMemorySize, AT_TOTAL);

    // 0) prep: split x, transpose+split weights
    {
        int n4 = BB * SS * DD / 4;
        split_kernel<<<(n4 + 255) / 256, 256>>>(x, xhi, xlo, n4);
        dim3 g1(3 * DD / 32, DD / 32);
        tsplit_kernel<<<g1, dim3(32, 8)>>>(W_qkv, wqh, wql, DD, 3 * DD);
        dim3 g2(DD / 32, DD / 32);
        tsplit_kernel<<<g2, dim3(32, 8)>>>(W_o, woh, wol, DD, DD);
    }

    // 1) QKV projection (tensor) — epilogue also emits bf16 hi/lo
    {
        dim3 grid(3 * DD / 128, BB * SS / 128);
        gemm3x_mma<<<grid, 256, GT_TOTAL>>>(xhi, xlo, wqh, wql, b_qkv, qkv_ptr,
                                            qhp, qlp, BB * SS, 3 * DD, DD);
    }

    // 2) V^T split (reads fp32 qkv)
    {
        dim3 gv(SS / 32, HDIM / 32, BB * HH);
        vT_kernel<<<gv, dim3(32, 8)>>>(qkv_ptr, vthp, vtlp);
    }

    // 3) fused tensorized attention (writes values hi/lo directly)
    {
        dim3 grid(SS / 32, HH, BB);
        attn_mma<<<grid, 256, AT_TOTAL>>>(qhp, qlp, vthp, vtlp, out_attn);
    }

    // 4) O-proj (tensor), reads values hi/lo from attn epilogue
    {
        dim3 grid(DD / 128, BB * SS / 128);
        gemm3x_mma<<<grid, 256, GT_TOTAL>>>(vhi, vlo, woh, wol, b_o, out_o,
                                            (__nv_bfloat16*)nullptr, (__nv_bfloat16*)nullptr,
                                            BB * SS, DD, DD);
    }
}

// round 6
// speedup vs baseline: 1.0335x; 1.0335x over previous
#include <cuda_runtime.h>
#include <cuda_bf16.h>

#define BB 4
#define SS 1024
#define HH 16
#define HDIM 64
#define DD 1024

// ---------------------------------------------------------------------------
// scratch (device globals — no allocation allowed)
// ---------------------------------------------------------------------------
__device__ float g_qkv[BB * SS * 3 * DD];   // [B,S,3D] fp32 (for vT)
__device__ __nv_bfloat16 g_xhi[BB * SS * DD];
__device__ __nv_bfloat16 g_xlo[BB * SS * DD];
__device__ __nv_bfloat16 g_wqT_hi[3 * DD * DD];
__device__ __nv_bfloat16 g_wqT_lo[3 * DD * DD];
__device__ __nv_bfloat16 g_woT_hi[DD * DD];
__device__ __nv_bfloat16 g_woT_lo[DD * DD];
__device__ __nv_bfloat16 g_vhi[BB * SS * DD];   // values hi (attn epilogue)
__device__ __nv_bfloat16 g_vlo[BB * SS * DD];
__device__ __nv_bfloat16 g_qh[BB * SS * 3 * DD];   // qkv split hi (gemm epilogue)
__device__ __nv_bfloat16 g_ql[BB * SS * 3 * DD];
__device__ __nv_bfloat16 g_vTh[BB * HH * HDIM * SS]; // V^T per (b,h): [64][S]
__device__ __nv_bfloat16 g_vTl[BB * HH * HDIM * SS];

// ---------------------------------------------------------------------------
__device__ __forceinline__ unsigned smem_u32(const void* p) {
    unsigned a;
    asm("{ .reg .u64 t; cvta.to.shared.u64 t, %1; cvt.u32.u64 %0, t; }" : "=r"(a) : "l"(p));
    return a;
}
#define SWZ128(o) ((o) ^ (((o) >> 3) & 0x70))
#define SWZ64(o)  ((o) ^ (((o) >> 3) & 0x30))

#define CP_ASYNC16(saddr, gptr) \
    asm volatile("cp.async.cg.shared.global [%0], [%1], 16;" :: "r"(saddr), "l"(gptr) : "memory")
#define CP_COMMIT() asm volatile("cp.async.commit_group;" ::: "memory")
#define CP_WAIT0()  asm volatile("cp.async.wait_group 0;" ::: "memory")

#define LDMX4(r0, r1, r2, r3, a) \
    asm volatile("ldmatrix.sync.aligned.m8n8.x4.shared.b16 {%0,%1,%2,%3}, [%4];" \
        : "=r"(r0), "=r"(r1), "=r"(r2), "=r"(r3) : "r"(a))

#define MMA16816(d, a, b0, b1) \
    asm volatile("mma.sync.aligned.m16n8k16.row.col.f32.bf16.bf16.f32 " \
        "{%0,%1,%2,%3}, {%4,%5,%6,%7}, {%8,%9}, {%0,%1,%2,%3};" \
        : "+f"((d)[0]), "+f"((d)[1]), "+f"((d)[2]), "+f"((d)[3]) \
        : "r"((a)[0]), "r"((a)[1]), "r"((a)[2]), "r"((a)[3]), "r"(b0), "r"(b1))

__device__ __forceinline__ unsigned pack_hi2(float x, float y, unsigned& lo) {
    __nv_bfloat16 hx = __float2bfloat16(x);
    __nv_bfloat16 hy = __float2bfloat16(y);
    __nv_bfloat16 lx = __float2bfloat16(x - __bfloat162float(hx));
    __nv_bfloat16 ly = __float2bfloat16(y - __bfloat162float(hy));
    lo = ((unsigned)__bfloat16_as_ushort(ly) << 16) | __bfloat16_as_ushort(lx);
    return ((unsigned)__bfloat16_as_ushort(hy) << 16) | __bfloat16_as_ushort(hx);
}
__device__ __forceinline__ float bflo(unsigned u) {
    return __bfloat162float(__ushort_as_bfloat16((unsigned short)(u & 0xFFFF)));
}
__device__ __forceinline__ float bfhi(unsigned u) {
    return __bfloat162float(__ushort_as_bfloat16((unsigned short)(u >> 16)));
}

// ---------------------------------------------------------------------------
__global__ __launch_bounds__(256) void split_kernel(
    const float* __restrict__ src, __nv_bfloat16* __restrict__ hi,
    __nv_bfloat16* __restrict__ lo, int n4)
{
    int i = blockIdx.x * 256 + threadIdx.x;
    if (i >= n4) return;
    float4 v = ((const float4*)src)[i];
    unsigned l0, l1, h0, h1;
    h0 = pack_hi2(v.x, v.y, l0);
    h1 = pack_hi2(v.z, v.w, l1);
    ((uint2*)hi)[i] = make_uint2(h0, h1);
    ((uint2*)lo)[i] = make_uint2(l0, l1);
}

__global__ __launch_bounds__(256) void tsplit_kernel(
    const float* __restrict__ W, __nv_bfloat16* __restrict__ hiT,
    __nv_bfloat16* __restrict__ loT, int K, int N)
{
    __shared__ float t[32][33];
    int k0 = blockIdx.y * 32, n0 = blockIdx.x * 32;
    int tx = threadIdx.x, ty = threadIdx.y;
    #pragma unroll
    for (int i = 0; i < 32; i += 8)
        t[ty + i][tx] = W[(size_t)(k0 + ty + i) * N + n0 + tx];
    __syncthreads();
    #pragma unroll
    for (int i = 0; i < 32; i += 8) {
        float v = t[tx][ty + i];
        __nv_bfloat16 h = __float2bfloat16(v);
        size_t o = (size_t)(n0 + ty + i) * K + k0 + tx;
        hiT[o] = h;
        loT[o] = __float2bfloat16(v - __bfloat162float(h));
    }
}

__global__ __launch_bounds__(256) void vT_kernel(
    const float* __restrict__ qkv, __nv_bfloat16* __restrict__ vTh,
    __nv_bfloat16* __restrict__ vTl)
{
    __shared__ float t[32][33];
    int s0 = blockIdx.x * 32, d0 = blockIdx.y * 32, bh = blockIdx.z;
    int b = bh >> 4, h = bh & 15;
    int tx = threadIdx.x, ty = threadIdx.y;
    #pragma unroll
    for (int i = 0; i < 32; i += 8)
        t[ty + i][tx] = qkv[(size_t)(b * SS + s0 + ty + i) * 3072 + h * 192 + 128 + d0 + tx];
    __syncthreads();
    #pragma unroll
    for (int i = 0; i < 32; i += 8) {
        float v = t[tx][ty + i];
        __nv_bfloat16 hh = __float2bfloat16(v);
        size_t o = (size_t)(bh * HDIM + d0 + ty + i) * SS + s0 + tx;
        vTh[o] = hh;
        vTl[o] = __float2bfloat16(v - __bfloat162float(hh));
    }
}

// ---------------------------------------------------------------------------
// Combined-pass GEMM: per K-chunk(32) stage holds Ahi|Alo|BThi|BTlo (8KB each).
// 64B rows, SWZ64. 2 stages, early-issue double buffer.
// ---------------------------------------------------------------------------
#define GS_STAGE 32768
#define GS_TOTAL 65536

__device__ __forceinline__ void gload64(const __nv_bfloat16* __restrict__ src,
                                        int rbase, int K, int kt, unsigned dst, int tid)
{
    #pragma unroll
    for (int i = 0; i < 2; i++) {
        int idx = tid + i * 256;
        int row = idx >> 2;
        int c16 = (idx & 3) * 16;
        CP_ASYNC16(dst + SWZ64((unsigned)(row * 64 + c16)),
                   (const char*)(src + (size_t)(rbase + row) * K + kt) + c16);
    }
}

__device__ __forceinline__ void prefetch_chunk(
    const __nv_bfloat16* __restrict__ Ahi, const __nv_bfloat16* __restrict__ Alo,
    const __nv_bfloat16* __restrict__ BThi, const __nv_bfloat16* __restrict__ BTlo,
    int brow, int bcol, int K, int kt, unsigned stage, int tid)
{
    gload64(Ahi, brow, K, kt, stage, tid);
    gload64(Alo, brow, K, kt, stage + 8192, tid);
    gload64(BThi, bcol, K, kt, stage + 16384, tid);
    gload64(BTlo, bcol, K, kt, stage + 24576, tid);
}

__global__ __launch_bounds__(256) void gemm3x_mma(
    const __nv_bfloat16* __restrict__ Ahi, const __nv_bfloat16* __restrict__ Alo,
    const __nv_bfloat16* __restrict__ BThi, const __nv_bfloat16* __restrict__ BTlo,
    const float* __restrict__ bias, float* __restrict__ C,
    __nv_bfloat16* __restrict__ Chi, __nv_bfloat16* __restrict__ Clo,
    int M, int N, int K)
{
    extern __shared__ char smem[];
    unsigned sb = smem_u32(smem);
    const int tid = threadIdx.x, w = tid >> 5, lane = tid & 31;
    const int brow = blockIdx.y * 128, bcol = blockIdx.x * 128;
    const int wm = (w >> 2) * 64;
    const int wn = (w & 3) * 32;
    const int lrow = lane & 15;
    const int lcol = (lane >> 4) * 16;

    const int nch = K >> 5;   // 32

    float acc[4][4][4] = {};

    prefetch_chunk(Ahi, Alo, BThi, BTlo, brow, bcol, K, 0, sb, tid);
    CP_COMMIT();
    CP_WAIT0();
    __syncthreads();

    for (int c = 0; c < nch; c++) {
        if (c + 1 < nch) {
            prefetch_chunk(Ahi, Alo, BThi, BTlo, brow, bcol, K, (c + 1) << 5,
                           sb + ((c + 1) & 1) * GS_STAGE, tid);
            CP_COMMIT();
        }
        unsigned base = sb + (c & 1) * GS_STAGE;
        #pragma unroll
        for (int ks = 0; ks < 2; ks++) {
            int kb = ks * 32;
            unsigned bH[2][4], bL[2][4];
            #pragma unroll
            for (int j2 = 0; j2 < 2; j2++) {
                unsigned off = (unsigned)((wn + j2 * 16 + lrow) * 64 + kb + lcol);
                LDMX4(bH[j2][0], bH[j2][1], bH[j2][2], bH[j2][3], base + 16384 + SWZ64(off));
                LDMX4(bL[j2][0], bL[j2][1], bL[j2][2], bL[j2][3], base + 24576 + SWZ64(off));
            }
            #pragma unroll
            for (int i = 0; i < 4; i++) {
                unsigned off = (unsigned)((wm + i * 16 + lrow) * 64 + kb + lcol);
                unsigned aH[4], aL[4];
                LDMX4(aH[0], aH[1], aH[2], aH[3], base + SWZ64(off));
                LDMX4(aL[0], aL[1], aL[2], aL[3], base + 8192 + SWZ64(off));
                #pragma unroll
                for (int j = 0; j < 4; j++) {
                    unsigned h0 = (j & 1) ? bH[j >> 1][1] : bH[j >> 1][0];
                    unsigned h1 = (j & 1) ? bH[j >> 1][3] : bH[j >> 1][2];
                    unsigned l0 = (j & 1) ? bL[j >> 1][1] : bL[j >> 1][0];
                    unsigned l1 = (j & 1) ? bL[j >> 1][3] : bL[j >> 1][2];
                    MMA16816(acc[i][j], aH, h0, h1);
                    MMA16816(acc[i][j], aL, h0, h1);
                    MMA16816(acc[i][j], aH, l0, l1);
                }
            }
        }
        if (c + 1 < nch) { CP_WAIT0(); }
        __syncthreads();
    }

    const int r0 = brow + wm + (lane >> 2);
    const int c0 = bcol + wn + (lane & 3) * 2;
    #pragma unroll
    for (int i = 0; i < 4; i++) {
        #pragma unroll
        for (int j = 0; j < 4; j++) {
            int col = c0 + j * 8;
            float bx = bias[col], by = bias[col + 1];
            float v00 = acc[i][j][0] + bx, v01 = acc[i][j][1] + by;
            float v10 = acc[i][j][2] + bx, v11 = acc[i][j][3] + by;
            size_t o0 = (size_t)(r0 + i * 16) * N + col;
            size_t o1 = (size_t)(r0 + i * 16 + 8) * N + col;
            *(float2*)&C[o0] = make_float2(v00, v01);
            *(float2*)&C[o1] = make_float2(v10, v11);
            if (Chi) {
                unsigned l0, l1;
                unsigned h0 = pack_hi2(v00, v01, l0);
                unsigned h1 = pack_hi2(v10, v11, l1);
                *(unsigned*)&Chi[o0] = h0;
                *(unsigned*)&Clo[o0] = l0;
                *(unsigned*)&Chi[o1] = h1;
                *(unsigned*)&Clo[o1] = l1;
            }
        }
    }
}

// ---------------------------------------------------------------------------
// Attention: logits tile stored as bf16 hi/lo with padded stride (2064B).
// Phase1: combined-pass QK^T. Phase2: softmax, pack unnormalized e, 1/sum to
// sStat. Phase3: combined-pass AV on packed P, scale by inv in epilogue.
// smem: sPh[0,66048) sPl[66048,132096) sStat[132096] sQH@132224 sQL@136320
//       KV bufs @140416: 2 x 32768
// ---------------------------------------------------------------------------
#define AT_SPL  66048
#define AT_STAT 132096
#define AT_QH   132224
#define AT_QL   136320
#define AT_KV   140416
#define AT_TOTAL 205952
#define PSTRIDE 2064

__device__ __forceinline__ void attn_load_k(
    const __nv_bfloat16* __restrict__ qh, const __nv_bfloat16* __restrict__ ql,
    int b, int h, int kb, unsigned dstH, unsigned dstL, int tid)
{
    #pragma unroll
    for (int i = 0; i < 4; i++) {
        int idx = tid + i * 256;
        int row = idx >> 3, c16 = (idx & 7) * 16;
        unsigned so = SWZ128((unsigned)(row * 128 + c16));
        CP_ASYNC16(dstH + so, (const char*)(qh + (size_t)(b * SS + kb + row) * 3072 + h * 192 + 64) + c16);
        CP_ASYNC16(dstL + so, (const char*)(ql + (size_t)(b * SS + kb + row) * 3072 + h * 192 + 64) + c16);
    }
}

// V chunk = 128 keys as two 64-key subtiles (8KB each), hi then lo
__device__ __forceinline__ void attn_load_v(
    const __nv_bfloat16* __restrict__ vTh, const __nv_bfloat16* __restrict__ vTl,
    int bh, int kb, unsigned dst, int tid)
{
    #pragma unroll
    for (int s = 0; s < 2; s++) {
        #pragma unroll
        for (int i = 0; i < 2; i++) {
            int idx = tid + i * 256;
            int row = idx >> 3, c16 = (idx & 7) * 16;
            unsigned so = SWZ128((unsigned)(row * 128 + c16));
            const char* gh = (const char*)(vTh + (size_t)(bh * HDIM + row) * SS + kb + s * 64) + c16;
            const char* gl = (const char*)(vTl + (size_t)(bh * HDIM + row) * SS + kb + s * 64) + c16;
            CP_ASYNC16(dst + s * 8192 + so, gh);
            CP_ASYNC16(dst + 16384 + s * 8192 + so, gl);
        }
    }
}

__global__ __launch_bounds__(256) void attn_mma(
    const __nv_bfloat16* __restrict__ qh, const __nv_bfloat16* __restrict__ ql,
    const __nv_bfloat16* __restrict__ vTh, const __nv_bfloat16* __restrict__ vTl,
    float* __restrict__ attn_out)
{
    extern __shared__ char smem[];
    unsigned sb = smem_u32(smem);
    float* sStat = (float*)(smem + AT_STAT);

    const int qt = blockIdx.x, h = blockIdx.y, b = blockIdx.z;
    const int bh = b * HH + h;
    const int q0 = qt * 32;
    const int tid = threadIdx.x, w = tid >> 5, lane = tid & 31;
    const int lrow = lane & 15, lcol = (lane >> 4) * 16;

    // ---- prologue: Q tile + K chunk 0
    {
        int row = tid >> 3, c16 = (tid & 7) * 16;
        unsigned so = SWZ128((unsigned)(row * 128 + c16));
        CP_ASYNC16(sb + AT_QH + so, (const char*)(qh + (size_t)(b * SS + q0 + row) * 3072 + h * 192) + c16);
        CP_ASYNC16(sb + AT_QL + so, (const char*)(ql + (size_t)(b * SS + q0 + row) * 3072 + h * 192) + c16);
    }
    attn_load_k(qh, ql, b, h, 0, sb + AT_KV, sb + AT_KV + 16384, tid);
    CP_COMMIT();
    CP_WAIT0();
    __syncthreads();

    // ---- phase 1: logits = 0.125 * Q K^T  (8 chunks of 128 keys)
    const int wm = (w >> 2) * 16;
    const int wn = (w & 3) * 32;
    for (int c = 0; c < 8; c++) {
        if (c + 1 < 8) {
            unsigned nb = sb + AT_KV + ((c + 1) & 1) * 32768;
            attn_load_k(qh, ql, b, h, (c + 1) * 128, nb, nb + 16384, tid);
            CP_COMMIT();
        }
        unsigned bufH = sb + AT_KV + (c & 1) * 32768;
        unsigned bufL = bufH + 16384;
        float acc[4][4] = {};
        #pragma unroll
        for (int ks = 0; ks < 4; ks++) {
            int kb = ks * 32;
            unsigned aoff = SWZ128((unsigned)((wm + lrow) * 128 + kb + lcol));
            unsigned aH[4], aL[4];
            LDMX4(aH[0], aH[1], aH[2], aH[3], sb + AT_QH + aoff);
            LDMX4(aL[0], aL[1], aL[2], aL[3], sb + AT_QL + aoff);
            unsigned bH[2][4], bL[2][4];
            #pragma unroll
            for (int j2 = 0; j2 < 2; j2++) {
                unsigned boff = SWZ128((unsigned)((wn + j2 * 16 + lrow) * 128 + kb + lcol));
                LDMX4(bH[j2][0], bH[j2][1], bH[j2][2], bH[j2][3], bufH + boff);
                LDMX4(bL[j2][0], bL[j2][1], bL[j2][2], bL[j2][3], bufL + boff);
            }
            #pragma unroll
            for (int j = 0; j < 4; j++) {
                unsigned h0 = (j & 1) ? bH[j >> 1][1] : bH[j >> 1][0];
                unsigned h1 = (j & 1) ? bH[j >> 1][3] : bH[j >> 1][2];
                unsigned l0 = (j & 1) ? bL[j >> 1][1] : bL[j >> 1][0];
                unsigned l1 = (j & 1) ? bL[j >> 1][3] : bL[j >> 1][2];
                MMA16816(acc[j], aH, h0, h1);
                MMA16816(acc[j], aL, h0, h1);
                MMA16816(acc[j], aH, l0, l1);
            }
        }
        // store logits (x0.125) as packed hi/lo
        int r0 = wm + (lane >> 2);
        int cb = c * 128 + wn + (lane & 3) * 2;
        #pragma unroll
        for (int j = 0; j < 4; j++) {
            int col = cb + j * 8;
            unsigned lp0, lp1;
            unsigned hp0 = pack_hi2(acc[j][0] * 0.125f, acc[j][1] * 0.125f, lp0);
            unsigned hp1 = pack_hi2(acc[j][2] * 0.125f, acc[j][3] * 0.125f, lp1);
            unsigned o0 = (unsigned)(r0 * PSTRIDE + col * 2);
            unsigned o1 = (unsigned)((r0 + 8) * PSTRIDE + col * 2);
            *(unsigned*)(smem + o0) = hp0;
            *(unsigned*)(smem + AT_SPL + o0) = lp0;
            *(unsigned*)(smem + o1) = hp1;
            *(unsigned*)(smem + AT_SPL + o1) = lp1;
        }
        if (c + 1 < 8) { CP_WAIT0(); }
        __syncthreads();
    }

    // ---- V chunk 0 prefetch overlaps softmax
    attn_load_v(vTh, vTl, bh, 0, sb + AT_KV, tid);
    CP_COMMIT();

    // ---- phase 2: softmax; attn out; pack unnormalized e; inv -> sStat
    for (int r = w; r < 32; r += 8) {
        float m = -1e30f;
        #pragma unroll 4
        for (int it = 0; it < 16; it++) {
            unsigned o = (unsigned)(r * PSTRIDE + it * 128 + lane * 4);
            unsigned uh = *(unsigned*)(smem + o);
            unsigned ul = *(unsigned*)(smem + AT_SPL + o);
            float l0 = bflo(uh) + bflo(ul);
            float l1 = bfhi(uh) + bfhi(ul);
            m = fmaxf(m, fmaxf(l0, l1));
        }
        #pragma unroll
        for (int o = 16; o > 0; o >>= 1) m = fmaxf(m, __shfl_xor_sync(0xFFFFFFFFu, m, o));
        float sum = 0.f;
        #pragma unroll 4
        for (int it = 0; it < 16; it++) {
            unsigned o = (unsigned)(r * PSTRIDE + it * 128 + lane * 4);
            unsigned uh = *(unsigned*)(smem + o);
            unsigned ul = *(unsigned*)(smem + AT_SPL + o);
            float e0 = __expf(bflo(uh) + bflo(ul) - m);
            float e1 = __expf(bfhi(uh) + bfhi(ul) - m);
            sum += e0 + e1;
            unsigned lp;
            unsigned hp = pack_hi2(e0, e1, lp);
            *(unsigned*)(smem + o) = hp;
            *(unsigned*)(smem + AT_SPL + o) = lp;
        }
        #pragma unroll
        for (int o = 16; o > 0; o >>= 1) sum += __shfl_xor_sync(0xFFFFFFFFu, sum, o);
        float inv = 1.0f / sum;
        if (lane == 0) sStat[r] = inv;
        size_t base = ((size_t)(bh * SS) + q0 + r) * SS;
        #pragma unroll 4
        for (int it = 0; it < 16; it++) {
            unsigned o = (unsigned)(r * PSTRIDE + it * 128 + lane * 4);
            unsigned uh = *(unsigned*)(smem + o);
            unsigned ul = *(unsigned*)(smem + AT_SPL + o);
            float v0 = (bflo(uh) + bflo(ul)) * inv;
            float v1 = (bfhi(uh) + bfhi(ul)) * inv;
            *(float2*)&attn_out[base + it * 64 + lane * 2] = make_float2(v0, v1);
        }
    }
    CP_WAIT0();
    __syncthreads();

    // ---- phase 3: AV (8 chunks of 128 keys) on packed unnormalized P
    const int wmv = (w >> 2) * 16;
    const int wnv = (w & 3) * 16;
    float vac[2][4] = {};
    for (int c = 0; c < 8; c++) {
        if (c + 1 < 8) {
            attn_load_v(vTh, vTl, bh, (c + 1) * 128, sb + AT_KV + ((c + 1) & 1) * 32768, tid);
            CP_COMMIT();
        }
        unsigned vbase = sb + AT_KV + (c & 1) * 32768;
        #pragma unroll
        for (int ks = 0; ks < 8; ks++) {
            int s = ks >> 2;
            int kb = (ks & 3) * 32;
            unsigned ao = (unsigned)((wmv + lrow) * PSTRIDE + c * 256 + ks * 32 + lcol);
            unsigned aH[4], aL[4];
            LDMX4(aH[0], aH[1], aH[2], aH[3], sb + ao);
            LDMX4(aL[0], aL[1], aL[2], aL[3], sb + AT_SPL + ao);
            unsigned bo = SWZ128((unsigned)((wnv + lrow) * 128 + kb + lcol));
            unsigned bH[4], bL[4];
            LDMX4(bH[0], bH[1], bH[2], bH[3], vbase + s * 8192 + bo);
            LDMX4(bL[0], bL[1], bL[2], bL[3], vbase + 16384 + s * 8192 + bo);
            MMA16816(vac[0], aH, bH[0], bH[2]);
            MMA16816(vac[1], aH, bH[1], bH[3]);
            MMA16816(vac[0], aL, bH[0], bH[2]);
            MMA16816(vac[1], aL, bH[1], bH[3]);
            MMA16816(vac[0], aH, bL[0], bL[2]);
            MMA16816(vac[1], aH, bL[1], bL[3]);
        }
        if (c + 1 < 8) { CP_WAIT0(); }
        __syncthreads();
    }

    // ---- epilogue: scale by inv, write bf16 hi/lo values
    {
        int r0 = wmv + (lane >> 2);
        float inv0 = sStat[r0], inv1 = sStat[r0 + 8];
        int c0 = wnv + (lane & 3) * 2;
        #pragma unroll
        for (int j = 0; j < 2; j++) {
            int col = h * 64 + c0 + j * 8;
            size_t o0 = (size_t)(b * SS + q0 + r0) * DD + col;
            size_t o1 = (size_t)(b * SS + q0 + r0 + 8) * DD + col;
            unsigned l0, l1;
            unsigned h0 = pack_hi2(vac[j][0] * inv0, vac[j][1] * inv0, l0);
            unsigned h1 = pack_hi2(vac[j][2] * inv1, vac[j][3] * inv1, l1);
            *(unsigned*)&g_vhi[o0] = h0;
            *(unsigned*)&g_vlo[o0] = l0;
            *(unsigned*)&g_vhi[o1] = h1;
            *(unsigned*)&g_vlo[o1] = l1;
        }
    }
}

// ---------------------------------------------------------------------------
extern "C" void kernel_launch(void* const* d_in, const int* in_sizes, int n_in,
                              void* d_out, int out_size)
{
    const float* x     = (const float*)d_in[0];
    const float* W_qkv = (const float*)d_in[1];
    const float* b_qkv = (const float*)d_in[2];
    const float* W_o   = (const float*)d_in[3];
    const float* b_o   = (const float*)d_in[4];

    float* out_o    = (float*)d_out;
    float* out_attn = (float*)d_out + (size_t)BB * SS * DD;

    float* qkv_ptr;
    __nv_bfloat16 *xhi, *xlo, *wqh, *wql, *woh, *wol, *vhi, *vlo;
    __nv_bfloat16 *qhp, *qlp, *vthp, *vtlp;
    cudaGetSymbolAddress((void**)&qkv_ptr, g_qkv);
    cudaGetSymbolAddress((void**)&xhi, g_xhi);
    cudaGetSymbolAddress((void**)&xlo, g_xlo);
    cudaGetSymbolAddress((void**)&wqh, g_wqT_hi);
    cudaGetSymbolAddress((void**)&wql, g_wqT_lo);
    cudaGetSymbolAddress((void**)&woh, g_woT_hi);
    cudaGetSymbolAddress((void**)&wol, g_woT_lo);
    cudaGetSymbolAddress((void**)&vhi, g_vhi);
    cudaGetSymbolAddress((void**)&vlo, g_vlo);
    cudaGetSymbolAddress((void**)&qhp, g_qh);
    cudaGetSymbolAddress((void**)&qlp, g_ql);
    cudaGetSymbolAddress((void**)&vthp, g_vTh);
    cudaGetSymbolAddress((void**)&vtlp, g_vTl);

    cudaFuncSetAttribute(gemm3x_mma, cudaFuncAttributeMaxDynamicSharedMemorySize, GS_TOTAL);
    cudaFuncSetAttribute(attn_mma, cudaFuncAttributeMaxDynamicSharedMemorySize, AT_TOTAL);

    // 0) prep
    {
        int n4 = BB * SS * DD / 4;
        split_kernel<<<(n4 + 255) / 256, 256>>>(x, xhi, xlo, n4);
        dim3 g1(3 * DD / 32, DD / 32);
        tsplit_kernel<<<g1, dim3(32, 8)>>>(W_qkv, wqh, wql, DD, 3 * DD);
        dim3 g2(DD / 32, DD / 32);
        tsplit_kernel<<<g2, dim3(32, 8)>>>(W_o, woh, wol, DD, DD);
    }

    // 1) QKV projection (tensor) — epilogue also emits bf16 hi/lo
    {
        dim3 grid(3 * DD / 128, BB * SS / 128);
        gemm3x_mma<<<grid, 256, GS_TOTAL>>>(xhi, xlo, wqh, wql, b_qkv, qkv_ptr,
                                            qhp, qlp, BB * SS, 3 * DD, DD);
    }

    // 2) V^T split
    {
        dim3 gv(SS / 32, HDIM / 32, BB * HH);
        vT_kernel<<<gv, dim3(32, 8)>>>(qkv_ptr, vthp, vtlp);
    }

    // 3) fused tensorized attention
    {
        dim3 grid(SS / 32, HH, BB);
        attn_mma<<<grid, 256, AT_TOTAL>>>(qhp, qlp, vthp, vtlp, out_attn);
    }

    // 4) O-proj (tensor)
    {
        dim3 grid(DD / 128, BB * SS / 128);
        gemm3x_mma<<<grid, 256, GS_TOTAL>>>(vhi, vlo, woh, wol, b_o, out_o,
                                            (__nv_bfloat16*)nullptr, (__nv_bfloat16*)nullptr,
                                            BB * SS, DD, DD);
    }
}